// round 1
// baseline (speedup 1.0000x reference)
#include <cuda_runtime.h>
#include <math_constants.h>

// Problem constants
#define BATCH   4
#define SEQ     2048
#define DMODEL  1024
#define NHEADS  16
#define HDIM    64
#define TOKENS  (BATCH * SEQ)   // 8192

#define LOG2E 1.4426950408889634f

// Scratch (allocation-free rule: __device__ globals)
__device__ float g_q  [TOKENS * DMODEL];
__device__ float g_k  [TOKENS * DMODEL];
__device__ float g_v  [TOKENS * DMODEL];
__device__ float g_ctx[TOKENS * DMODEL];

// ---------------------------------------------------------------------------
// SGEMM (NT): C[m,n] = sum_k A[m,k] * B[n,k] (+ bias[n])
// A: [M,K] row-major, B: [N,K] row-major (i.e. torch Linear weight), C: [M,N]
// Tiles: BM=BN=128, BK=8, 256 threads, 8x8 per-thread register tile.
// ---------------------------------------------------------------------------
__global__ __launch_bounds__(256) void sgemm_nt(
    const float* __restrict__ A, const float* __restrict__ B,
    const float* __restrict__ bias, float* __restrict__ C,
    int M, int N, int K)
{
    __shared__ float As[8][132];   // [k][m], padded to kill store conflicts
    __shared__ float Bs[8][132];   // [k][n]

    const int tid = threadIdx.x;
    const int tx  = tid & 15;      // 0..15 -> n
    const int ty  = tid >> 4;      // 0..15 -> m
    const int bm  = blockIdx.y * 128;
    const int bn  = blockIdx.x * 128;

    const int lrow = tid >> 1;         // 0..127
    const int lcol = (tid & 1) * 4;    // 0 or 4

    const float* Ag = A + (size_t)(bm + lrow) * K + lcol;
    const float* Bg = B + (size_t)(bn + lrow) * K + lcol;

    float acc[8][8];
#pragma unroll
    for (int i = 0; i < 8; i++)
#pragma unroll
        for (int j = 0; j < 8; j++) acc[i][j] = 0.f;

    for (int k0 = 0; k0 < K; k0 += 8) {
        float4 a4 = *(const float4*)(Ag + k0);
        float4 b4 = *(const float4*)(Bg + k0);
        As[lcol + 0][lrow] = a4.x;
        As[lcol + 1][lrow] = a4.y;
        As[lcol + 2][lrow] = a4.z;
        As[lcol + 3][lrow] = a4.w;
        Bs[lcol + 0][lrow] = b4.x;
        Bs[lcol + 1][lrow] = b4.y;
        Bs[lcol + 2][lrow] = b4.z;
        Bs[lcol + 3][lrow] = b4.w;
        __syncthreads();

#pragma unroll
        for (int k = 0; k < 8; k++) {
            float4 a0 = *(const float4*)&As[k][ty * 8];
            float4 a1 = *(const float4*)&As[k][ty * 8 + 4];
            float4 b0 = *(const float4*)&Bs[k][tx * 8];
            float4 b1 = *(const float4*)&Bs[k][tx * 8 + 4];
            float a[8] = {a0.x, a0.y, a0.z, a0.w, a1.x, a1.y, a1.z, a1.w};
            float b[8] = {b0.x, b0.y, b0.z, b0.w, b1.x, b1.y, b1.z, b1.w};
#pragma unroll
            for (int i = 0; i < 8; i++)
#pragma unroll
                for (int j = 0; j < 8; j++)
                    acc[i][j] = fmaf(a[i], b[j], acc[i][j]);
        }
        __syncthreads();
    }

    float bv[8];
#pragma unroll
    for (int j = 0; j < 8; j++)
        bv[j] = bias ? bias[bn + tx * 8 + j] : 0.f;

#pragma unroll
    for (int i = 0; i < 8; i++) {
        float* Crow = C + (size_t)(bm + ty * 8 + i) * N + bn + tx * 8;
        float4 o0 = make_float4(acc[i][0] + bv[0], acc[i][1] + bv[1],
                                acc[i][2] + bv[2], acc[i][3] + bv[3]);
        float4 o1 = make_float4(acc[i][4] + bv[4], acc[i][5] + bv[5],
                                acc[i][6] + bv[6], acc[i][7] + bv[7]);
        *(float4*)(Crow)     = o0;
        *(float4*)(Crow + 4) = o1;
    }
}

// ---------------------------------------------------------------------------
// Flash attention (causal), fp32, online softmax.
// Layouts: Q/K/V/O as [token, DMODEL]; head h occupies cols [h*64, h*64+64).
// Block: 256 threads (16x16), one (b, h, 64-row q tile). Iterates k tiles of
// 64 up to (and incl.) the diagonal tile. Register tiles 4x4 for both GEMMs.
// SMEM (dynamic): Qs[d][r] 64x68, Ks[d][j] 64x68, Ps[j][r] 64x68, Vs[j][d] 64x64.
// Pads of 68 keep float4 (16B) alignment per row (68*4 = 272 = 17*16).
// ---------------------------------------------------------------------------
__global__ __launch_bounds__(256) void flash_attn_kernel(
    const float* __restrict__ Q, const float* __restrict__ K,
    const float* __restrict__ V, float* __restrict__ O)
{
    extern __shared__ float sm[];
    float* Qs = sm;                 // [64][68] (d-major)
    float* Ks = sm + 64 * 68;       // [64][68] (d-major)
    float* Ps = sm + 2 * 64 * 68;   // [64][68] (P^T: [j][r])
    float* Vs = sm + 3 * 64 * 68;   // [64][64] ([j][d])

    const int tid = threadIdx.x;
    const int tx  = tid & 15;       // 0..15 -> cols (k idx / hd idx), *4
    const int ty  = tid >> 4;       // 0..15 -> rows (q idx), *4
    const int qt  = blockIdx.x;
    const int h   = blockIdx.y;
    const int b   = blockIdx.z;

    const int q0 = b * SEQ + qt * 64;           // global token base of q tile
    const float* Qg = Q + (size_t)q0 * DMODEL + h * HDIM;

    // Load Q tile transposed into Qs[d][r], pre-scaled by 1/sqrt(HD)=0.125
    for (int i = tid; i < 64 * 16; i += 256) {
        int r = i >> 4;
        int c = (i & 15) * 4;
        float4 v4 = *(const float4*)(Qg + (size_t)r * DMODEL + c);
        Qs[(c + 0) * 68 + r] = v4.x * 0.125f;
        Qs[(c + 1) * 68 + r] = v4.y * 0.125f;
        Qs[(c + 2) * 68 + r] = v4.z * 0.125f;
        Qs[(c + 3) * 68 + r] = v4.w * 0.125f;
    }

    float o_acc[4][4];
    float m_i[4], l_i[4];
#pragma unroll
    for (int i = 0; i < 4; i++) {
        m_i[i] = -CUDART_INF_F;
        l_i[i] = 0.f;
#pragma unroll
        for (int j = 0; j < 4; j++) o_acc[i][j] = 0.f;
    }

    for (int kt = 0; kt <= qt; kt++) {
        __syncthreads();  // prior iter's reads of Ks/Vs/Ps complete

        const int k0 = b * SEQ + kt * 64;
        const float* Kg = K + (size_t)k0 * DMODEL + h * HDIM;
        const float* Vg = V + (size_t)k0 * DMODEL + h * HDIM;
        for (int i = tid; i < 64 * 16; i += 256) {
            int r = i >> 4;
            int c = (i & 15) * 4;
            float4 k4 = *(const float4*)(Kg + (size_t)r * DMODEL + c);
            Ks[(c + 0) * 68 + r] = k4.x;
            Ks[(c + 1) * 68 + r] = k4.y;
            Ks[(c + 2) * 68 + r] = k4.z;
            Ks[(c + 3) * 68 + r] = k4.w;
            float4 v4 = *(const float4*)(Vg + (size_t)r * DMODEL + c);
            *(float4*)&Vs[r * 64 + c] = v4;
        }
        __syncthreads();

        // S tile: s[i][j] = sum_d Qs[d][ty*4+i] * Ks[d][tx*4+j]  (pre-scaled)
        float s[4][4];
#pragma unroll
        for (int i = 0; i < 4; i++)
#pragma unroll
            for (int j = 0; j < 4; j++) s[i][j] = 0.f;

#pragma unroll 16
        for (int d = 0; d < 64; d++) {
            float4 qa = *(const float4*)&Qs[d * 68 + ty * 4];
            float4 kb = *(const float4*)&Ks[d * 68 + tx * 4];
            float a[4] = {qa.x, qa.y, qa.z, qa.w};
            float bb[4] = {kb.x, kb.y, kb.z, kb.w};
#pragma unroll
            for (int i = 0; i < 4; i++)
#pragma unroll
                for (int j = 0; j < 4; j++)
                    s[i][j] = fmaf(a[i], bb[j], s[i][j]);
        }

        // Causal mask on the diagonal tile
        if (kt == qt) {
#pragma unroll
            for (int i = 0; i < 4; i++)
#pragma unroll
                for (int j = 0; j < 4; j++)
                    if (tx * 4 + j > ty * 4 + i) s[i][j] = -CUDART_INF_F;
        }

        // Row max (reduce 4 local cols, then butterfly over the 16 tx lanes)
        float rmax[4];
#pragma unroll
        for (int i = 0; i < 4; i++)
            rmax[i] = fmaxf(fmaxf(s[i][0], s[i][1]), fmaxf(s[i][2], s[i][3]));
#pragma unroll
        for (int off = 8; off >= 1; off >>= 1)
#pragma unroll
            for (int i = 0; i < 4; i++)
                rmax[i] = fmaxf(rmax[i], __shfl_xor_sync(0xffffffffu, rmax[i], off));

        float alpha[4];
#pragma unroll
        for (int i = 0; i < 4; i++) {
            float mn = fmaxf(m_i[i], rmax[i]);
            alpha[i] = exp2f((m_i[i] - mn) * LOG2E);
            m_i[i] = mn;
        }

        float p[4][4];
        float rsum[4] = {0.f, 0.f, 0.f, 0.f};
#pragma unroll
        for (int i = 0; i < 4; i++)
#pragma unroll
            for (int j = 0; j < 4; j++) {
                p[i][j] = exp2f((s[i][j] - m_i[i]) * LOG2E);
                rsum[i] += p[i][j];
            }
#pragma unroll
        for (int off = 8; off >= 1; off >>= 1)
#pragma unroll
            for (int i = 0; i < 4; i++)
                rsum[i] += __shfl_xor_sync(0xffffffffu, rsum[i], off);

#pragma unroll
        for (int i = 0; i < 4; i++) {
            l_i[i] = l_i[i] * alpha[i] + rsum[i];
#pragma unroll
            for (int j = 0; j < 4; j++) o_acc[i][j] *= alpha[i];
        }

        // Store P^T: Ps[j][r]
#pragma unroll
        for (int i = 0; i < 4; i++)
#pragma unroll
            for (int j = 0; j < 4; j++)
                Ps[(tx * 4 + j) * 68 + (ty * 4 + i)] = p[i][j];
        __syncthreads();

        // O += P @ V : o_acc[i][jj], rows r=ty*4+i, hd cols d=tx*4+jj
#pragma unroll 16
        for (int j = 0; j < 64; j++) {
            float4 pa = *(const float4*)&Ps[j * 68 + ty * 4];
            float4 vb = *(const float4*)&Vs[j * 64 + tx * 4];
            float a[4] = {pa.x, pa.y, pa.z, pa.w};
            float bb[4] = {vb.x, vb.y, vb.z, vb.w};
#pragma unroll
            for (int i = 0; i < 4; i++)
#pragma unroll
                for (int jj = 0; jj < 4; jj++)
                    o_acc[i][jj] = fmaf(a[i], bb[jj], o_acc[i][jj]);
        }
    }

    // Epilogue: normalize and store ctx[token, h*64 + d]
#pragma unroll
    for (int i = 0; i < 4; i++) {
        float inv = 1.f / l_i[i];
        float* Og = O + (size_t)(q0 + ty * 4 + i) * DMODEL + h * HDIM + tx * 4;
        float4 o4 = make_float4(o_acc[i][0] * inv, o_acc[i][1] * inv,
                                o_acc[i][2] * inv, o_acc[i][3] * inv);
        *(float4*)Og = o4;
    }
}

// ---------------------------------------------------------------------------
// Launch
// ---------------------------------------------------------------------------
extern "C" void kernel_launch(void* const* d_in, const int* in_sizes, int n_in,
                              void* d_out, int out_size)
{
    const float* x  = (const float*)d_in[0];
    const float* wq = (const float*)d_in[1];
    const float* wk = (const float*)d_in[2];
    const float* wv = (const float*)d_in[3];
    const float* wo = (const float*)d_in[4];
    const float* bo = (const float*)d_in[5];
    float* out = (float*)d_out;

    float *q, *k, *v, *ctx;
    cudaGetSymbolAddress((void**)&q,   g_q);
    cudaGetSymbolAddress((void**)&k,   g_k);
    cudaGetSymbolAddress((void**)&v,   g_v);
    cudaGetSymbolAddress((void**)&ctx, g_ctx);

    dim3 gemm_grid(DMODEL / 128, TOKENS / 128);

    sgemm_nt<<<gemm_grid, 256>>>(x, wq, nullptr, q, TOKENS, DMODEL, DMODEL);
    sgemm_nt<<<gemm_grid, 256>>>(x, wk, nullptr, k, TOKENS, DMODEL, DMODEL);
    sgemm_nt<<<gemm_grid, 256>>>(x, wv, nullptr, v, TOKENS, DMODEL, DMODEL);

    const int flash_smem = (3 * 64 * 68 + 64 * 64) * (int)sizeof(float); // 68608
    cudaFuncSetAttribute(flash_attn_kernel,
                         cudaFuncAttributeMaxDynamicSharedMemorySize, flash_smem);
    flash_attn_kernel<<<dim3(SEQ / 64, NHEADS, BATCH), 256, flash_smem>>>(q, k, v, ctx);

    sgemm_nt<<<gemm_grid, 256>>>(ctx, wo, bo, out, TOKENS, DMODEL, DMODEL);
}

// round 3
// speedup vs baseline: 1.4545x; 1.4545x over previous
#include <cuda_runtime.h>
#include <cuda_bf16.h>
#include <math_constants.h>
#include <cstdint>

// Problem constants
#define BATCH   4
#define SEQ     2048
#define DMODEL  1024
#define NHEADS  16
#define HDIM    64
#define TOKENS  (BATCH * SEQ)   // 8192

#define LOG2E 1.4426950408889634f

// ---------------------------------------------------------------------------
// Scratch (allocation-free rule: __device__ globals)
// ---------------------------------------------------------------------------
__device__ float g_q  [TOKENS * DMODEL];
__device__ float g_k  [TOKENS * DMODEL];
__device__ float g_v  [TOKENS * DMODEL];
__device__ float g_ctx[TOKENS * DMODEL];

__device__ __nv_bfloat16 g_xhi[TOKENS * DMODEL];
__device__ __nv_bfloat16 g_xlo[TOKENS * DMODEL];
__device__ __nv_bfloat16 g_chi[TOKENS * DMODEL];
__device__ __nv_bfloat16 g_clo[TOKENS * DMODEL];
__device__ __nv_bfloat16 g_wqhi[DMODEL * DMODEL];
__device__ __nv_bfloat16 g_wqlo[DMODEL * DMODEL];
__device__ __nv_bfloat16 g_wkhi[DMODEL * DMODEL];
__device__ __nv_bfloat16 g_wklo[DMODEL * DMODEL];
__device__ __nv_bfloat16 g_wvhi[DMODEL * DMODEL];
__device__ __nv_bfloat16 g_wvlo[DMODEL * DMODEL];
__device__ __nv_bfloat16 g_wohi[DMODEL * DMODEL];
__device__ __nv_bfloat16 g_wolo[DMODEL * DMODEL];

// ---------------------------------------------------------------------------
// PTX helpers (sm_80-baseline only: cp.async, ldmatrix, mma.sync)
// ---------------------------------------------------------------------------
__device__ __forceinline__ uint32_t smem_u32(const void* p) {
    uint32_t a;
    asm("{ .reg .u64 t; cvta.to.shared.u64 t, %1; cvt.u32.u64 %0, t; }"
        : "=r"(a) : "l"(p));
    return a;
}

__device__ __forceinline__ void cp_async16(uint32_t smem, const void* gmem) {
    asm volatile("cp.async.cg.shared.global [%0], [%1], 16;\n"
                 :: "r"(smem), "l"(gmem));
}
#define CP_COMMIT() asm volatile("cp.async.commit_group;\n" ::: "memory")
#define CP_WAIT(n)  asm volatile("cp.async.wait_group %0;\n" :: "n"(n) : "memory")

__device__ __forceinline__ void ldsm_x4(uint32_t* r, uint32_t addr) {
    asm volatile("ldmatrix.sync.aligned.m8n8.x4.shared.b16 {%0,%1,%2,%3}, [%4];"
                 : "=r"(r[0]), "=r"(r[1]), "=r"(r[2]), "=r"(r[3]) : "r"(addr));
}

__device__ __forceinline__ void mma_bf16(float* c, const uint32_t* a,
                                         uint32_t b0, uint32_t b1) {
    asm volatile(
        "mma.sync.aligned.m16n8k16.row.col.f32.bf16.bf16.f32 "
        "{%0,%1,%2,%3}, {%4,%5,%6,%7}, {%8,%9}, {%0,%1,%2,%3};"
        : "+f"(c[0]), "+f"(c[1]), "+f"(c[2]), "+f"(c[3])
        : "r"(a[0]), "r"(a[1]), "r"(a[2]), "r"(a[3]), "r"(b0), "r"(b1));
}

// ---------------------------------------------------------------------------
// Split fp32 -> (bf16 hi, bf16 lo).  n must be a multiple of 4.
// ---------------------------------------------------------------------------
__global__ void split_bf16_kernel(const float* __restrict__ in,
                                  __nv_bfloat16* __restrict__ hi,
                                  __nv_bfloat16* __restrict__ lo, int n)
{
    int i = (blockIdx.x * blockDim.x + threadIdx.x) * 4;
    if (i >= n) return;
    float4 v = *(const float4*)(in + i);
    __nv_bfloat16 h0 = __float2bfloat16(v.x);
    __nv_bfloat16 h1 = __float2bfloat16(v.y);
    __nv_bfloat16 h2 = __float2bfloat16(v.z);
    __nv_bfloat16 h3 = __float2bfloat16(v.w);
    __nv_bfloat16 l0 = __float2bfloat16(v.x - __bfloat162float(h0));
    __nv_bfloat16 l1 = __float2bfloat16(v.y - __bfloat162float(h1));
    __nv_bfloat16 l2 = __float2bfloat16(v.z - __bfloat162float(h2));
    __nv_bfloat16 l3 = __float2bfloat16(v.w - __bfloat162float(h3));
    ((__nv_bfloat162*)(hi + i))[0] = __nv_bfloat162(h0, h1);
    ((__nv_bfloat162*)(hi + i))[1] = __nv_bfloat162(h2, h3);
    ((__nv_bfloat162*)(lo + i))[0] = __nv_bfloat162(l0, l1);
    ((__nv_bfloat162*)(lo + i))[1] = __nv_bfloat162(l2, l3);
}

// ---------------------------------------------------------------------------
// Tensor-core bf16x3 GEMM (NT): C[m,n] = sum_k A[m,k]*B[n,k] (+bias), fp32 out.
// CTA 128x128, BK=32, 256 threads (8 warps, 2x4), warp tile 64x32.
// 3-stage cp.async pipeline. SMEM rows padded to 80B (conflict-free ldmatrix).
// ---------------------------------------------------------------------------
#define GK_BK       32
#define GK_ROW_B    80                     // padded row pitch in bytes
#define GK_TILE_B   (128 * GK_ROW_B)       // 10240
#define GK_STAGE_B  (4 * GK_TILE_B)        // 40960 (Ahi, Alo, Bhi, Blo)
#define GK_STAGES   3
#define GK_SMEM     (GK_STAGES * GK_STAGE_B)  // 122880

__global__ __launch_bounds__(256) void gemm_mma_bf16x3(
    const __nv_bfloat16* __restrict__ Ahi, const __nv_bfloat16* __restrict__ Alo,
    const __nv_bfloat16* __restrict__ Bhi, const __nv_bfloat16* __restrict__ Blo,
    const float* __restrict__ bias, float* __restrict__ C,
    int M, int N, int K)
{
    extern __shared__ char smem[];
    const uint32_t sbase = smem_u32(smem);
    const int tid  = threadIdx.x;
    const int wid  = tid >> 5;
    const int lane = tid & 31;
    const int warp_m = wid >> 2;     // 0..1
    const int warp_n = wid & 3;      // 0..3
    const int bm = blockIdx.y * 128;
    const int bn = blockIdx.x * 128;

    const __nv_bfloat16* srcs[4] = {Ahi, Alo, Bhi, Blo};
    const int nchunks = K / GK_BK;   // 32 for K=1024

    float acc[4][4][4];
#pragma unroll
    for (int i = 0; i < 4; i++)
#pragma unroll
        for (int j = 0; j < 4; j++)
#pragma unroll
            for (int r = 0; r < 4; r++) acc[i][j][r] = 0.f;

    auto load_chunk = [&](int c, int st) {
        const int k0 = c * GK_BK;
#pragma unroll
        for (int t = 0; t < 4; t++) {
            const __nv_bfloat16* src = srcs[t];
            const int rbase = (t < 2) ? bm : bn;
            const uint32_t tb = sbase + st * GK_STAGE_B + t * GK_TILE_B;
#pragma unroll
            for (int i = tid; i < 512; i += 256) {
                const int r = i >> 2;
                const int q = i & 3;
                cp_async16(tb + r * GK_ROW_B + q * 16,
                           src + (size_t)(rbase + r) * K + k0 + q * 8);
            }
        }
        CP_COMMIT();
    };

    load_chunk(0, 0);
    load_chunk(1, 1);

    const uint32_t lrow16 = (uint32_t)(lane & 15);
    const uint32_t lcolb  = (uint32_t)((lane >> 4) << 4);  // 0 or 16 bytes

    for (int c = 0; c < nchunks; c++) {
        const int st = c % GK_STAGES;
        CP_WAIT(1);
        __syncthreads();
        if (c + 2 < nchunks) load_chunk(c + 2, (c + 2) % GK_STAGES);

        const uint32_t stg = sbase + st * GK_STAGE_B;
        const uint32_t a_r = (uint32_t)(warp_m * 64) + lrow16;
        const uint32_t b_r = (uint32_t)(warp_n * 32) + lrow16;

#pragma unroll
        for (int ks = 0; ks < 2; ks++) {
            const uint32_t kb = lcolb + ks * 32;
            uint32_t ah[4][4], al[4][4], bh[2][4], bl[2][4];
#pragma unroll
            for (int mi = 0; mi < 4; mi++) {
                uint32_t ro = (a_r + mi * 16) * GK_ROW_B + kb;
                ldsm_x4(ah[mi], stg + 0 * GK_TILE_B + ro);
                ldsm_x4(al[mi], stg + 1 * GK_TILE_B + ro);
            }
#pragma unroll
            for (int p = 0; p < 2; p++) {
                uint32_t ro = (b_r + p * 16) * GK_ROW_B + kb;
                ldsm_x4(bh[p], stg + 2 * GK_TILE_B + ro);
                ldsm_x4(bl[p], stg + 3 * GK_TILE_B + ro);
            }
#pragma unroll
            for (int mi = 0; mi < 4; mi++)
#pragma unroll
                for (int ni = 0; ni < 4; ni++) {
                    const int p = ni >> 1, s = ni & 1;
                    mma_bf16(acc[mi][ni], ah[mi], bh[p][s], bh[p][s + 2]);
                    mma_bf16(acc[mi][ni], ah[mi], bl[p][s], bl[p][s + 2]);
                    mma_bf16(acc[mi][ni], al[mi], bh[p][s], bh[p][s + 2]);
                }
        }
        __syncthreads();
    }

    // Epilogue: direct register -> gmem stores (float2 per frag half)
    const int er = lane >> 2;            // 0..7
    const int ec = (lane & 3) * 2;       // 0,2,4,6
#pragma unroll
    for (int mi = 0; mi < 4; mi++) {
        const int row0 = bm + warp_m * 64 + mi * 16 + er;
#pragma unroll
        for (int ni = 0; ni < 4; ni++) {
            const int col = bn + warp_n * 32 + ni * 8 + ec;
            float b0 = 0.f, b1 = 0.f;
            if (bias) { b0 = bias[col]; b1 = bias[col + 1]; }
            float2 v0 = make_float2(acc[mi][ni][0] + b0, acc[mi][ni][1] + b1);
            float2 v1 = make_float2(acc[mi][ni][2] + b0, acc[mi][ni][3] + b1);
            *(float2*)(C + (size_t)row0 * N + col)       = v0;
            *(float2*)(C + (size_t)(row0 + 8) * N + col) = v1;
        }
    }
}

// ---------------------------------------------------------------------------
// Flash attention (causal), fp32, online softmax (unchanged; known good).
// ---------------------------------------------------------------------------
__global__ __launch_bounds__(256) void flash_attn_kernel(
    const float* __restrict__ Q, const float* __restrict__ K,
    const float* __restrict__ V, float* __restrict__ O)
{
    extern __shared__ float sm[];
    float* Qs = sm;                 // [64][68] (d-major)
    float* Ks = sm + 64 * 68;       // [64][68] (d-major)
    float* Ps = sm + 2 * 64 * 68;   // [64][68] (P^T: [j][r])
    float* Vs = sm + 3 * 64 * 68;   // [64][64] ([j][d])

    const int tid = threadIdx.x;
    const int tx  = tid & 15;
    const int ty  = tid >> 4;
    const int qt  = blockIdx.x;
    const int h   = blockIdx.y;
    const int b   = blockIdx.z;

    const int q0 = b * SEQ + qt * 64;
    const float* Qg = Q + (size_t)q0 * DMODEL + h * HDIM;

    for (int i = tid; i < 64 * 16; i += 256) {
        int r = i >> 4;
        int c = (i & 15) * 4;
        float4 v4 = *(const float4*)(Qg + (size_t)r * DMODEL + c);
        Qs[(c + 0) * 68 + r] = v4.x * 0.125f;
        Qs[(c + 1) * 68 + r] = v4.y * 0.125f;
        Qs[(c + 2) * 68 + r] = v4.z * 0.125f;
        Qs[(c + 3) * 68 + r] = v4.w * 0.125f;
    }

    float o_acc[4][4];
    float m_i[4], l_i[4];
#pragma unroll
    for (int i = 0; i < 4; i++) {
        m_i[i] = -CUDART_INF_F;
        l_i[i] = 0.f;
#pragma unroll
        for (int j = 0; j < 4; j++) o_acc[i][j] = 0.f;
    }

    for (int kt = 0; kt <= qt; kt++) {
        __syncthreads();

        const int k0 = b * SEQ + kt * 64;
        const float* Kg = K + (size_t)k0 * DMODEL + h * HDIM;
        const float* Vg = V + (size_t)k0 * DMODEL + h * HDIM;
        for (int i = tid; i < 64 * 16; i += 256) {
            int r = i >> 4;
            int c = (i & 15) * 4;
            float4 k4 = *(const float4*)(Kg + (size_t)r * DMODEL + c);
            Ks[(c + 0) * 68 + r] = k4.x;
            Ks[(c + 1) * 68 + r] = k4.y;
            Ks[(c + 2) * 68 + r] = k4.z;
            Ks[(c + 3) * 68 + r] = k4.w;
            float4 v4 = *(const float4*)(Vg + (size_t)r * DMODEL + c);
            *(float4*)&Vs[r * 64 + c] = v4;
        }
        __syncthreads();

        float s[4][4];
#pragma unroll
        for (int i = 0; i < 4; i++)
#pragma unroll
            for (int j = 0; j < 4; j++) s[i][j] = 0.f;

#pragma unroll 16
        for (int d = 0; d < 64; d++) {
            float4 qa = *(const float4*)&Qs[d * 68 + ty * 4];
            float4 kb = *(const float4*)&Ks[d * 68 + tx * 4];
            float a[4] = {qa.x, qa.y, qa.z, qa.w};
            float bb[4] = {kb.x, kb.y, kb.z, kb.w};
#pragma unroll
            for (int i = 0; i < 4; i++)
#pragma unroll
                for (int j = 0; j < 4; j++)
                    s[i][j] = fmaf(a[i], bb[j], s[i][j]);
        }

        if (kt == qt) {
#pragma unroll
            for (int i = 0; i < 4; i++)
#pragma unroll
                for (int j = 0; j < 4; j++)
                    if (tx * 4 + j > ty * 4 + i) s[i][j] = -CUDART_INF_F;
        }

        float rmax[4];
#pragma unroll
        for (int i = 0; i < 4; i++)
            rmax[i] = fmaxf(fmaxf(s[i][0], s[i][1]), fmaxf(s[i][2], s[i][3]));
#pragma unroll
        for (int off = 8; off >= 1; off >>= 1)
#pragma unroll
            for (int i = 0; i < 4; i++)
                rmax[i] = fmaxf(rmax[i], __shfl_xor_sync(0xffffffffu, rmax[i], off));

        float alpha[4];
#pragma unroll
        for (int i = 0; i < 4; i++) {
            float mn = fmaxf(m_i[i], rmax[i]);
            alpha[i] = exp2f((m_i[i] - mn) * LOG2E);
            m_i[i] = mn;
        }

        float p[4][4];
        float rsum[4] = {0.f, 0.f, 0.f, 0.f};
#pragma unroll
        for (int i = 0; i < 4; i++)
#pragma unroll
            for (int j = 0; j < 4; j++) {
                p[i][j] = exp2f((s[i][j] - m_i[i]) * LOG2E);
                rsum[i] += p[i][j];
            }
#pragma unroll
        for (int off = 8; off >= 1; off >>= 1)
#pragma unroll
            for (int i = 0; i < 4; i++)
                rsum[i] += __shfl_xor_sync(0xffffffffu, rsum[i], off);

#pragma unroll
        for (int i = 0; i < 4; i++) {
            l_i[i] = l_i[i] * alpha[i] + rsum[i];
#pragma unroll
            for (int j = 0; j < 4; j++) o_acc[i][j] *= alpha[i];
        }

#pragma unroll
        for (int i = 0; i < 4; i++)
#pragma unroll
            for (int j = 0; j < 4; j++)
                Ps[(tx * 4 + j) * 68 + (ty * 4 + i)] = p[i][j];
        __syncthreads();

#pragma unroll 16
        for (int j = 0; j < 64; j++) {
            float4 pa = *(const float4*)&Ps[j * 68 + ty * 4];
            float4 vb = *(const float4*)&Vs[j * 64 + tx * 4];
            float a[4] = {pa.x, pa.y, pa.z, pa.w};
            float bb[4] = {vb.x, vb.y, vb.z, vb.w};
#pragma unroll
            for (int i = 0; i < 4; i++)
#pragma unroll
                for (int jj = 0; jj < 4; jj++)
                    o_acc[i][jj] = fmaf(a[i], bb[jj], o_acc[i][jj]);
        }
    }

#pragma unroll
    for (int i = 0; i < 4; i++) {
        float inv = 1.f / l_i[i];
        float* Og = O + (size_t)(q0 + ty * 4 + i) * DMODEL + h * HDIM + tx * 4;
        float4 o4 = make_float4(o_acc[i][0] * inv, o_acc[i][1] * inv,
                                o_acc[i][2] * inv, o_acc[i][3] * inv);
        *(float4*)Og = o4;
    }
}

// ---------------------------------------------------------------------------
// Launch
// ---------------------------------------------------------------------------
extern "C" void kernel_launch(void* const* d_in, const int* in_sizes, int n_in,
                              void* d_out, int out_size)
{
    const float* x  = (const float*)d_in[0];
    const float* wq = (const float*)d_in[1];
    const float* wk = (const float*)d_in[2];
    const float* wv = (const float*)d_in[3];
    const float* wo = (const float*)d_in[4];
    const float* bo = (const float*)d_in[5];
    float* out = (float*)d_out;

    float *q, *k, *v, *ctx;
    cudaGetSymbolAddress((void**)&q,   g_q);
    cudaGetSymbolAddress((void**)&k,   g_k);
    cudaGetSymbolAddress((void**)&v,   g_v);
    cudaGetSymbolAddress((void**)&ctx, g_ctx);

    __nv_bfloat16 *xhi, *xlo, *chi, *clo;
    __nv_bfloat16 *wqhi, *wqlo, *wkhi, *wklo, *wvhi, *wvlo, *wohi, *wolo;
    cudaGetSymbolAddress((void**)&xhi,  g_xhi);
    cudaGetSymbolAddress((void**)&xlo,  g_xlo);
    cudaGetSymbolAddress((void**)&chi,  g_chi);
    cudaGetSymbolAddress((void**)&clo,  g_clo);
    cudaGetSymbolAddress((void**)&wqhi, g_wqhi);
    cudaGetSymbolAddress((void**)&wqlo, g_wqlo);
    cudaGetSymbolAddress((void**)&wkhi, g_wkhi);
    cudaGetSymbolAddress((void**)&wklo, g_wklo);
    cudaGetSymbolAddress((void**)&wvhi, g_wvhi);
    cudaGetSymbolAddress((void**)&wvlo, g_wvlo);
    cudaGetSymbolAddress((void**)&wohi, g_wohi);
    cudaGetSymbolAddress((void**)&wolo, g_wolo);

    const int nx = TOKENS * DMODEL;  // 8388608
    const int nw = DMODEL * DMODEL;  // 1048576

    split_bf16_kernel<<<nx / 4 / 256, 256>>>(x,  xhi,  xlo,  nx);
    split_bf16_kernel<<<nw / 4 / 256, 256>>>(wq, wqhi, wqlo, nw);
    split_bf16_kernel<<<nw / 4 / 256, 256>>>(wk, wkhi, wklo, nw);
    split_bf16_kernel<<<nw / 4 / 256, 256>>>(wv, wvhi, wvlo, nw);
    split_bf16_kernel<<<nw / 4 / 256, 256>>>(wo, wohi, wolo, nw);

    cudaFuncSetAttribute(gemm_mma_bf16x3,
                         cudaFuncAttributeMaxDynamicSharedMemorySize, GK_SMEM);
    dim3 ggrid(DMODEL / 128, TOKENS / 128);
    gemm_mma_bf16x3<<<ggrid, 256, GK_SMEM>>>(xhi, xlo, wqhi, wqlo, nullptr, q,
                                             TOKENS, DMODEL, DMODEL);
    gemm_mma_bf16x3<<<ggrid, 256, GK_SMEM>>>(xhi, xlo, wkhi, wklo, nullptr, k,
                                             TOKENS, DMODEL, DMODEL);
    gemm_mma_bf16x3<<<ggrid, 256, GK_SMEM>>>(xhi, xlo, wvhi, wvlo, nullptr, v,
                                             TOKENS, DMODEL, DMODEL);

    const int flash_smem = (3 * 64 * 68 + 64 * 64) * (int)sizeof(float);
    cudaFuncSetAttribute(flash_attn_kernel,
                         cudaFuncAttributeMaxDynamicSharedMemorySize, flash_smem);
    flash_attn_kernel<<<dim3(SEQ / 64, NHEADS, BATCH), 256, flash_smem>>>(q, k, v, ctx);

    split_bf16_kernel<<<nx / 4 / 256, 256>>>(ctx, chi, clo, nx);
    gemm_mma_bf16x3<<<ggrid, 256, GK_SMEM>>>(chi, clo, wohi, wolo, bo, out,
                                             TOKENS, DMODEL, DMODEL);
}

// round 5
// speedup vs baseline: 2.2615x; 1.5548x over previous
#include <cuda_runtime.h>
#include <cuda_bf16.h>
#include <math_constants.h>
#include <cstdint>

// Problem constants
#define BATCH   4
#define SEQ     2048
#define DMODEL  1024
#define NHEADS  16
#define HDIM    64
#define TOKENS  (BATCH * SEQ)   // 8192

#define LOG2E 1.4426950408889634f

// ---------------------------------------------------------------------------
// Scratch (allocation-free rule: __device__ globals)
// ---------------------------------------------------------------------------
__device__ float g_q  [TOKENS * DMODEL];
__device__ float g_k  [TOKENS * DMODEL];
__device__ float g_v  [TOKENS * DMODEL];
__device__ float g_ctx[TOKENS * DMODEL];

__device__ __nv_bfloat16 g_xhi[TOKENS * DMODEL];
__device__ __nv_bfloat16 g_xlo[TOKENS * DMODEL];
__device__ __nv_bfloat16 g_chi[TOKENS * DMODEL];
__device__ __nv_bfloat16 g_clo[TOKENS * DMODEL];
__device__ __nv_bfloat16 g_wqhi[DMODEL * DMODEL];
__device__ __nv_bfloat16 g_wqlo[DMODEL * DMODEL];
__device__ __nv_bfloat16 g_wkhi[DMODEL * DMODEL];
__device__ __nv_bfloat16 g_wklo[DMODEL * DMODEL];
__device__ __nv_bfloat16 g_wvhi[DMODEL * DMODEL];
__device__ __nv_bfloat16 g_wvlo[DMODEL * DMODEL];
__device__ __nv_bfloat16 g_wohi[DMODEL * DMODEL];
__device__ __nv_bfloat16 g_wolo[DMODEL * DMODEL];

// ---------------------------------------------------------------------------
// PTX helpers (sm_80-baseline only: cp.async, ldmatrix, mma.sync)
// ---------------------------------------------------------------------------
__device__ __forceinline__ uint32_t smem_u32(const void* p) {
    uint32_t a;
    asm("{ .reg .u64 t; cvta.to.shared.u64 t, %1; cvt.u32.u64 %0, t; }"
        : "=r"(a) : "l"(p));
    return a;
}

__device__ __forceinline__ void cp_async16(uint32_t smem, const void* gmem) {
    asm volatile("cp.async.cg.shared.global [%0], [%1], 16;\n"
                 :: "r"(smem), "l"(gmem));
}
#define CP_COMMIT() asm volatile("cp.async.commit_group;\n" ::: "memory")
#define CP_WAIT(n)  asm volatile("cp.async.wait_group %0;\n" :: "n"(n) : "memory")

__device__ __forceinline__ void ldsm_x4(uint32_t* r, uint32_t addr) {
    asm volatile("ldmatrix.sync.aligned.m8n8.x4.shared.b16 {%0,%1,%2,%3}, [%4];"
                 : "=r"(r[0]), "=r"(r[1]), "=r"(r[2]), "=r"(r[3]) : "r"(addr));
}

__device__ __forceinline__ void ldsm_x4_trans(uint32_t* r, uint32_t addr) {
    asm volatile("ldmatrix.sync.aligned.m8n8.x4.trans.shared.b16 {%0,%1,%2,%3}, [%4];"
                 : "=r"(r[0]), "=r"(r[1]), "=r"(r[2]), "=r"(r[3]) : "r"(addr));
}

__device__ __forceinline__ void mma_bf16(float* c, const uint32_t* a,
                                         uint32_t b0, uint32_t b1) {
    asm volatile(
        "mma.sync.aligned.m16n8k16.row.col.f32.bf16.bf16.f32 "
        "{%0,%1,%2,%3}, {%4,%5,%6,%7}, {%8,%9}, {%0,%1,%2,%3};"
        : "+f"(c[0]), "+f"(c[1]), "+f"(c[2]), "+f"(c[3])
        : "r"(a[0]), "r"(a[1]), "r"(a[2]), "r"(a[3]), "r"(b0), "r"(b1));
}

__device__ __forceinline__ uint32_t pack_bf16(float x, float y) {
    __nv_bfloat162 t = __floats2bfloat162_rn(x, y);
    return *(uint32_t*)&t;
}

// ---------------------------------------------------------------------------
// Split fp32 -> (bf16 hi, bf16 lo).
// ---------------------------------------------------------------------------
__global__ void split_bf16_kernel(const float* __restrict__ in,
                                  __nv_bfloat16* __restrict__ hi,
                                  __nv_bfloat16* __restrict__ lo, int n)
{
    int i = (blockIdx.x * blockDim.x + threadIdx.x) * 4;
    if (i >= n) return;
    float4 v = *(const float4*)(in + i);
    __nv_bfloat16 h0 = __float2bfloat16(v.x);
    __nv_bfloat16 h1 = __float2bfloat16(v.y);
    __nv_bfloat16 h2 = __float2bfloat16(v.z);
    __nv_bfloat16 h3 = __float2bfloat16(v.w);
    __nv_bfloat16 l0 = __float2bfloat16(v.x - __bfloat162float(h0));
    __nv_bfloat16 l1 = __float2bfloat16(v.y - __bfloat162float(h1));
    __nv_bfloat16 l2 = __float2bfloat16(v.z - __bfloat162float(h2));
    __nv_bfloat16 l3 = __float2bfloat16(v.w - __bfloat162float(h3));
    ((__nv_bfloat162*)(hi + i))[0] = __nv_bfloat162(h0, h1);
    ((__nv_bfloat162*)(hi + i))[1] = __nv_bfloat162(h2, h3);
    ((__nv_bfloat162*)(lo + i))[0] = __nv_bfloat162(l0, l1);
    ((__nv_bfloat162*)(lo + i))[1] = __nv_bfloat162(l2, l3);
}

// ---------------------------------------------------------------------------
// Tensor-core bf16x3 GEMM (NT) — unchanged (known good).
// ---------------------------------------------------------------------------
#define GK_BK       32
#define GK_ROW_B    80
#define GK_TILE_B   (128 * GK_ROW_B)
#define GK_STAGE_B  (4 * GK_TILE_B)
#define GK_STAGES   3
#define GK_SMEM     (GK_STAGES * GK_STAGE_B)

__global__ __launch_bounds__(256) void gemm_mma_bf16x3(
    const __nv_bfloat16* __restrict__ Ahi, const __nv_bfloat16* __restrict__ Alo,
    const __nv_bfloat16* __restrict__ Bhi, const __nv_bfloat16* __restrict__ Blo,
    const float* __restrict__ bias, float* __restrict__ C,
    int M, int N, int K)
{
    extern __shared__ char smem[];
    const uint32_t sbase = smem_u32(smem);
    const int tid  = threadIdx.x;
    const int wid  = tid >> 5;
    const int lane = tid & 31;
    const int warp_m = wid >> 2;
    const int warp_n = wid & 3;
    const int bm = blockIdx.y * 128;
    const int bn = blockIdx.x * 128;

    const __nv_bfloat16* srcs[4] = {Ahi, Alo, Bhi, Blo};
    const int nchunks = K / GK_BK;

    float acc[4][4][4];
#pragma unroll
    for (int i = 0; i < 4; i++)
#pragma unroll
        for (int j = 0; j < 4; j++)
#pragma unroll
            for (int r = 0; r < 4; r++) acc[i][j][r] = 0.f;

    auto load_chunk = [&](int c, int st) {
        const int k0 = c * GK_BK;
#pragma unroll
        for (int t = 0; t < 4; t++) {
            const __nv_bfloat16* src = srcs[t];
            const int rbase = (t < 2) ? bm : bn;
            const uint32_t tb = sbase + st * GK_STAGE_B + t * GK_TILE_B;
#pragma unroll
            for (int i = tid; i < 512; i += 256) {
                const int r = i >> 2;
                const int q = i & 3;
                cp_async16(tb + r * GK_ROW_B + q * 16,
                           src + (size_t)(rbase + r) * K + k0 + q * 8);
            }
        }
        CP_COMMIT();
    };

    load_chunk(0, 0);
    load_chunk(1, 1);

    const uint32_t lrow16 = (uint32_t)(lane & 15);
    const uint32_t lcolb  = (uint32_t)((lane >> 4) << 4);

    for (int c = 0; c < nchunks; c++) {
        const int st = c % GK_STAGES;
        CP_WAIT(1);
        __syncthreads();
        if (c + 2 < nchunks) load_chunk(c + 2, (c + 2) % GK_STAGES);

        const uint32_t stg = sbase + st * GK_STAGE_B;
        const uint32_t a_r = (uint32_t)(warp_m * 64) + lrow16;
        const uint32_t b_r = (uint32_t)(warp_n * 32) + lrow16;

#pragma unroll
        for (int ks = 0; ks < 2; ks++) {
            const uint32_t kb = lcolb + ks * 32;
            uint32_t ah[4][4], al[4][4], bh[2][4], bl[2][4];
#pragma unroll
            for (int mi = 0; mi < 4; mi++) {
                uint32_t ro = (a_r + mi * 16) * GK_ROW_B + kb;
                ldsm_x4(ah[mi], stg + 0 * GK_TILE_B + ro);
                ldsm_x4(al[mi], stg + 1 * GK_TILE_B + ro);
            }
#pragma unroll
            for (int p = 0; p < 2; p++) {
                uint32_t ro = (b_r + p * 16) * GK_ROW_B + kb;
                ldsm_x4(bh[p], stg + 2 * GK_TILE_B + ro);
                ldsm_x4(bl[p], stg + 3 * GK_TILE_B + ro);
            }
#pragma unroll
            for (int mi = 0; mi < 4; mi++)
#pragma unroll
                for (int ni = 0; ni < 4; ni++) {
                    const int p = ni >> 1, s = ni & 1;
                    mma_bf16(acc[mi][ni], ah[mi], bh[p][s], bh[p][s + 2]);
                    mma_bf16(acc[mi][ni], ah[mi], bl[p][s], bl[p][s + 2]);
                    mma_bf16(acc[mi][ni], al[mi], bh[p][s], bh[p][s + 2]);
                }
        }
        __syncthreads();
    }

    const int er = lane >> 2;
    const int ec = (lane & 3) * 2;
#pragma unroll
    for (int mi = 0; mi < 4; mi++) {
        const int row0 = bm + warp_m * 64 + mi * 16 + er;
#pragma unroll
        for (int ni = 0; ni < 4; ni++) {
            const int col = bn + warp_n * 32 + ni * 8 + ec;
            float b0 = 0.f, b1 = 0.f;
            if (bias) { b0 = bias[col]; b1 = bias[col + 1]; }
            float2 v0 = make_float2(acc[mi][ni][0] + b0, acc[mi][ni][1] + b1);
            float2 v1 = make_float2(acc[mi][ni][2] + b0, acc[mi][ni][3] + b1);
            *(float2*)(C + (size_t)row0 * N + col)       = v0;
            *(float2*)(C + (size_t)(row0 + 8) * N + col) = v1;
        }
    }
}

// ---------------------------------------------------------------------------
// Tensor-core flash attention (causal), bf16x3 MMA, fp32 softmax.
// C-fragment layout (m16n8): c0=(r,c), c1=(r,c+1), c2=(r+8,c), c3=(r+8,c+1)
// => regs {0,1} belong to q-row r (stats index 0), regs {2,3} to r+8 (index 1).
// ---------------------------------------------------------------------------
#define FA_PITCH 72    // bf16 elements per SMEM row (144 bytes)

__global__ __launch_bounds__(256) void flash_mma_kernel(
    const float* __restrict__ Q, const float* __restrict__ K,
    const float* __restrict__ V, float* __restrict__ O)
{
    __shared__ __nv_bfloat16 Ks_hi[64 * FA_PITCH];
    __shared__ __nv_bfloat16 Ks_lo[64 * FA_PITCH];
    __shared__ __nv_bfloat16 Vs_hi[64 * FA_PITCH];
    __shared__ __nv_bfloat16 Vs_lo[64 * FA_PITCH];

    const int tid  = threadIdx.x;
    const int wid  = tid >> 5;
    const int lane = tid & 31;
    const int qt = blockIdx.x;     // 0..15
    const int h  = blockIdx.y;
    const int b  = blockIdx.z;

    const int q0_tok = b * SEQ + qt * 128;
    const int qrow_w = qt * 128 + wid * 16;        // warp's first q row (seq pos)
    const float* Qg = Q + (size_t)(q0_tok + wid * 16) * DMODEL + h * HDIM;

    // ---- Q A-fragments (hi/lo), loaded once, pre-scaled by 1/8 ----
    // A-frag layout: a0=(g,c), a1=(g+8,c), a2=(g,c+8), a3=(g+8,c+8)
    uint32_t qhi[4][4], qlo[4][4];
    {
        const int r = lane >> 2;
        const int c = (lane & 3) * 2;
#pragma unroll
        for (int t = 0; t < 4; t++)
#pragma unroll
            for (int i = 0; i < 4; i++) {
                const int rr = r + (i & 1) * 8;
                const int cc = t * 16 + c + (i >> 1) * 8;
                float2 v = *(const float2*)(Qg + (size_t)rr * DMODEL + cc);
                v.x *= 0.125f; v.y *= 0.125f;
                float hx = __bfloat162float(__float2bfloat16(v.x));
                float hy = __bfloat162float(__float2bfloat16(v.y));
                qhi[t][i] = pack_bf16(v.x, v.y);
                qlo[t][i] = pack_bf16(v.x - hx, v.y - hy);
            }
    }

    float o[8][4];
    float m[2], l[2];
#pragma unroll
    for (int i = 0; i < 8; i++)
#pragma unroll
        for (int j = 0; j < 4; j++) o[i][j] = 0.f;
    m[0] = m[1] = -CUDART_INF_F;
    l[0] = l[1] = 0.f;

    const uint32_t ks_hi_b = smem_u32(Ks_hi);
    const uint32_t ks_lo_b = smem_u32(Ks_lo);
    const uint32_t vs_hi_b = smem_u32(Vs_hi);
    const uint32_t vs_lo_b = smem_u32(Vs_lo);

    // ldmatrix lane offsets (bytes)
    const uint32_t k_loff = (uint32_t)(((lane & 7) + ((lane >> 4) << 3)) * (FA_PITCH * 2)
                                       + (((lane >> 3) & 1) << 4));
    const uint32_t v_loff = (uint32_t)(((lane & 7) + (((lane >> 3) & 1) << 3)) * (FA_PITCH * 2)
                                       + ((lane >> 4) << 4));

    const int nkt = 2 * qt + 2;    // 64-key tiles to process

    for (int kt = 0; kt < nkt; kt++) {
        const int kb = kt * 64;    // first key (seq pos) of this tile
        __syncthreads();

        // ---- load + convert K,V tile: fp32 gmem -> bf16 hi/lo SMEM ----
        {
            const int tok0 = b * SEQ + kb;
            const float* Kg = K + (size_t)tok0 * DMODEL + h * HDIM;
            const float* Vg = V + (size_t)tok0 * DMODEL + h * HDIM;
#pragma unroll
            for (int i = tid; i < 1024; i += 256) {
                const int r  = i >> 4;
                const int c4 = (i & 15) * 4;
                const int so = r * FA_PITCH + c4;
                float4 kv = *(const float4*)(Kg + (size_t)r * DMODEL + c4);
                float4 vv = *(const float4*)(Vg + (size_t)r * DMODEL + c4);
                __nv_bfloat16 kh0 = __float2bfloat16(kv.x), kh1 = __float2bfloat16(kv.y);
                __nv_bfloat16 kh2 = __float2bfloat16(kv.z), kh3 = __float2bfloat16(kv.w);
                *(__nv_bfloat162*)&Ks_hi[so]     = __nv_bfloat162(kh0, kh1);
                *(__nv_bfloat162*)&Ks_hi[so + 2] = __nv_bfloat162(kh2, kh3);
                *(__nv_bfloat162*)&Ks_lo[so]     = __nv_bfloat162(
                    __float2bfloat16(kv.x - __bfloat162float(kh0)),
                    __float2bfloat16(kv.y - __bfloat162float(kh1)));
                *(__nv_bfloat162*)&Ks_lo[so + 2] = __nv_bfloat162(
                    __float2bfloat16(kv.z - __bfloat162float(kh2)),
                    __float2bfloat16(kv.w - __bfloat162float(kh3)));
                __nv_bfloat16 vh0 = __float2bfloat16(vv.x), vh1 = __float2bfloat16(vv.y);
                __nv_bfloat16 vh2 = __float2bfloat16(vv.z), vh3 = __float2bfloat16(vv.w);
                *(__nv_bfloat162*)&Vs_hi[so]     = __nv_bfloat162(vh0, vh1);
                *(__nv_bfloat162*)&Vs_hi[so + 2] = __nv_bfloat162(vh2, vh3);
                *(__nv_bfloat162*)&Vs_lo[so]     = __nv_bfloat162(
                    __float2bfloat16(vv.x - __bfloat162float(vh0)),
                    __float2bfloat16(vv.y - __bfloat162float(vh1)));
                *(__nv_bfloat162*)&Vs_lo[so + 2] = __nv_bfloat162(
                    __float2bfloat16(vv.z - __bfloat162float(vh2)),
                    __float2bfloat16(vv.w - __bfloat162float(vh3)));
            }
        }
        __syncthreads();

        // Fully-masked tile for this warp? (all keys > all of warp's q rows)
        if (kb > qrow_w + 15) continue;

        // ---- S = Q K^T (bf16x3), warp tile 16 x 64 ----
        float s[8][4];
#pragma unroll
        for (int i = 0; i < 8; i++)
#pragma unroll
            for (int j = 0; j < 4; j++) s[i][j] = 0.f;

#pragma unroll
        for (int t = 0; t < 4; t++) {
#pragma unroll
            for (int pp = 0; pp < 4; pp++) {
                const uint32_t ro = (uint32_t)(pp * 16 * (FA_PITCH * 2) + t * 32) + k_loff;
                uint32_t kh[4], kl[4];
                ldsm_x4(kh, ks_hi_b + ro);
                ldsm_x4(kl, ks_lo_b + ro);
                mma_bf16(s[2 * pp],     qhi[t], kh[0], kh[1]);
                mma_bf16(s[2 * pp],     qhi[t], kl[0], kl[1]);
                mma_bf16(s[2 * pp],     qlo[t], kh[0], kh[1]);
                mma_bf16(s[2 * pp + 1], qhi[t], kh[2], kh[3]);
                mma_bf16(s[2 * pp + 1], qhi[t], kl[2], kl[3]);
                mma_bf16(s[2 * pp + 1], qlo[t], kh[2], kh[3]);
            }
        }

        // ---- causal mask: c-reg i -> row = g + (i>>1)*8, col = c + (i&1) ----
        const int row_g0 = qrow_w + (lane >> 2);
        if (kb + 63 > qrow_w) {
#pragma unroll
            for (int nt = 0; nt < 8; nt++) {
                const int colb = kb + nt * 8 + (lane & 3) * 2;
#pragma unroll
                for (int i = 0; i < 4; i++) {
                    const int row = row_g0 + (i >> 1) * 8;
                    const int col = colb + (i & 1);
                    if (col > row) s[nt][i] = -CUDART_INF_F;
                }
            }
        }

        // ---- online softmax: regs {0,1} -> row r (idx 0), {2,3} -> r+8 (idx 1) ----
        float rmax[2];
        rmax[0] = rmax[1] = -CUDART_INF_F;
#pragma unroll
        for (int nt = 0; nt < 8; nt++) {
            rmax[0] = fmaxf(rmax[0], fmaxf(s[nt][0], s[nt][1]));
            rmax[1] = fmaxf(rmax[1], fmaxf(s[nt][2], s[nt][3]));
        }
#pragma unroll
        for (int off = 1; off <= 2; off <<= 1) {
            rmax[0] = fmaxf(rmax[0], __shfl_xor_sync(0xffffffffu, rmax[0], off));
            rmax[1] = fmaxf(rmax[1], __shfl_xor_sync(0xffffffffu, rmax[1], off));
        }

        float alpha[2], rsum[2];
#pragma unroll
        for (int i = 0; i < 2; i++) {
            float mn = fmaxf(m[i], rmax[i]);
            alpha[i] = exp2f((m[i] - mn) * LOG2E);
            m[i] = mn;
            rsum[i] = 0.f;
        }

#pragma unroll
        for (int nt = 0; nt < 8; nt++) {
            s[nt][0] = exp2f((s[nt][0] - m[0]) * LOG2E);
            s[nt][1] = exp2f((s[nt][1] - m[0]) * LOG2E);
            s[nt][2] = exp2f((s[nt][2] - m[1]) * LOG2E);
            s[nt][3] = exp2f((s[nt][3] - m[1]) * LOG2E);
            rsum[0] += s[nt][0] + s[nt][1];
            rsum[1] += s[nt][2] + s[nt][3];
        }
#pragma unroll
        for (int off = 1; off <= 2; off <<= 1) {
            rsum[0] += __shfl_xor_sync(0xffffffffu, rsum[0], off);
            rsum[1] += __shfl_xor_sync(0xffffffffu, rsum[1], off);
        }
        l[0] = l[0] * alpha[0] + rsum[0];
        l[1] = l[1] * alpha[1] + rsum[1];
#pragma unroll
        for (int nt = 0; nt < 8; nt++) {
            o[nt][0] *= alpha[0]; o[nt][1] *= alpha[0];
            o[nt][2] *= alpha[1]; o[nt][3] *= alpha[1];
        }

        // ---- O += P V (bf16x3); P C-frags -> A-frags in registers ----
        // A-frag tile t (keys 16t..16t+15):
        //   a0 = {c0,c1} of nt=2t      (row g,   keys +0..7)
        //   a1 = {c2,c3} of nt=2t      (row g+8, keys +0..7)
        //   a2 = {c0,c1} of nt=2t+1    (row g,   keys +8..15)
        //   a3 = {c2,c3} of nt=2t+1    (row g+8, keys +8..15)
#pragma unroll
        for (int t = 0; t < 4; t++) {
            uint32_t ahi[4], alo[4];
            {
                float x0 = s[2 * t][0],     x1 = s[2 * t][1];
                float x2 = s[2 * t][2],     x3 = s[2 * t][3];
                float y0 = s[2 * t + 1][0], y1 = s[2 * t + 1][1];
                float y2 = s[2 * t + 1][2], y3 = s[2 * t + 1][3];
                float hx0 = __bfloat162float(__float2bfloat16(x0));
                float hx1 = __bfloat162float(__float2bfloat16(x1));
                float hx2 = __bfloat162float(__float2bfloat16(x2));
                float hx3 = __bfloat162float(__float2bfloat16(x3));
                float hy0 = __bfloat162float(__float2bfloat16(y0));
                float hy1 = __bfloat162float(__float2bfloat16(y1));
                float hy2 = __bfloat162float(__float2bfloat16(y2));
                float hy3 = __bfloat162float(__float2bfloat16(y3));
                ahi[0] = pack_bf16(x0, x1);  alo[0] = pack_bf16(x0 - hx0, x1 - hx1);
                ahi[1] = pack_bf16(x2, x3);  alo[1] = pack_bf16(x2 - hx2, x3 - hx3);
                ahi[2] = pack_bf16(y0, y1);  alo[2] = pack_bf16(y0 - hy0, y1 - hy1);
                ahi[3] = pack_bf16(y2, y3);  alo[3] = pack_bf16(y2 - hy2, y3 - hy3);
            }
#pragma unroll
            for (int dp = 0; dp < 4; dp++) {
                const uint32_t ro = (uint32_t)(t * 16 * (FA_PITCH * 2) + dp * 32) + v_loff;
                uint32_t bh[4], bl[4];
                ldsm_x4_trans(bh, vs_hi_b + ro);
                ldsm_x4_trans(bl, vs_lo_b + ro);
                mma_bf16(o[2 * dp],     ahi, bh[0], bh[1]);
                mma_bf16(o[2 * dp],     ahi, bl[0], bl[1]);
                mma_bf16(o[2 * dp],     alo, bh[0], bh[1]);
                mma_bf16(o[2 * dp + 1], ahi, bh[2], bh[3]);
                mma_bf16(o[2 * dp + 1], ahi, bl[2], bl[3]);
                mma_bf16(o[2 * dp + 1], alo, bh[2], bh[3]);
            }
        }
    }

    // ---- epilogue: normalize and store ctx ----
    const float inv0 = 1.f / l[0];
    const float inv1 = 1.f / l[1];
    const int orow = q0_tok + wid * 16 + (lane >> 2);
    float* Ob = O + (size_t)orow * DMODEL + h * HDIM + (lane & 3) * 2;
#pragma unroll
    for (int nt = 0; nt < 8; nt++) {
        *(float2*)(Ob + nt * 8)                      = make_float2(o[nt][0] * inv0, o[nt][1] * inv0);
        *(float2*)(Ob + nt * 8 + (size_t)8 * DMODEL) = make_float2(o[nt][2] * inv1, o[nt][3] * inv1);
    }
}

// ---------------------------------------------------------------------------
// Launch
// ---------------------------------------------------------------------------
extern "C" void kernel_launch(void* const* d_in, const int* in_sizes, int n_in,
                              void* d_out, int out_size)
{
    const float* x  = (const float*)d_in[0];
    const float* wq = (const float*)d_in[1];
    const float* wk = (const float*)d_in[2];
    const float* wv = (const float*)d_in[3];
    const float* wo = (const float*)d_in[4];
    const float* bo = (const float*)d_in[5];
    float* out = (float*)d_out;

    float *q, *k, *v, *ctx;
    cudaGetSymbolAddress((void**)&q,   g_q);
    cudaGetSymbolAddress((void**)&k,   g_k);
    cudaGetSymbolAddress((void**)&v,   g_v);
    cudaGetSymbolAddress((void**)&ctx, g_ctx);

    __nv_bfloat16 *xhi, *xlo, *chi, *clo;
    __nv_bfloat16 *wqhi, *wqlo, *wkhi, *wklo, *wvhi, *wvlo, *wohi, *wolo;
    cudaGetSymbolAddress((void**)&xhi,  g_xhi);
    cudaGetSymbolAddress((void**)&xlo,  g_xlo);
    cudaGetSymbolAddress((void**)&chi,  g_chi);
    cudaGetSymbolAddress((void**)&clo,  g_clo);
    cudaGetSymbolAddress((void**)&wqhi, g_wqhi);
    cudaGetSymbolAddress((void**)&wqlo, g_wqlo);
    cudaGetSymbolAddress((void**)&wkhi, g_wkhi);
    cudaGetSymbolAddress((void**)&wklo, g_wklo);
    cudaGetSymbolAddress((void**)&wvhi, g_wvhi);
    cudaGetSymbolAddress((void**)&wvlo, g_wvlo);
    cudaGetSymbolAddress((void**)&wohi, g_wohi);
    cudaGetSymbolAddress((void**)&wolo, g_wolo);

    const int nx = TOKENS * DMODEL;
    const int nw = DMODEL * DMODEL;

    split_bf16_kernel<<<nx / 4 / 256, 256>>>(x,  xhi,  xlo,  nx);
    split_bf16_kernel<<<nw / 4 / 256, 256>>>(wq, wqhi, wqlo, nw);
    split_bf16_kernel<<<nw / 4 / 256, 256>>>(wk, wkhi, wklo, nw);
    split_bf16_kernel<<<nw / 4 / 256, 256>>>(wv, wvhi, wvlo, nw);
    split_bf16_kernel<<<nw / 4 / 256, 256>>>(wo, wohi, wolo, nw);

    cudaFuncSetAttribute(gemm_mma_bf16x3,
                         cudaFuncAttributeMaxDynamicSharedMemorySize, GK_SMEM);
    dim3 ggrid(DMODEL / 128, TOKENS / 128);
    gemm_mma_bf16x3<<<ggrid, 256, GK_SMEM>>>(xhi, xlo, wqhi, wqlo, nullptr, q,
                                             TOKENS, DMODEL, DMODEL);
    gemm_mma_bf16x3<<<ggrid, 256, GK_SMEM>>>(xhi, xlo, wkhi, wklo, nullptr, k,
                                             TOKENS, DMODEL, DMODEL);
    gemm_mma_bf16x3<<<ggrid, 256, GK_SMEM>>>(xhi, xlo, wvhi, wvlo, nullptr, v,
                                             TOKENS, DMODEL, DMODEL);

    flash_mma_kernel<<<dim3(SEQ / 128, NHEADS, BATCH), 256>>>(q, k, v, ctx);

    split_bf16_kernel<<<nx / 4 / 256, 256>>>(ctx, chi, clo, nx);
    gemm_mma_bf16x3<<<ggrid, 256, GK_SMEM>>>(chi, clo, wohi, wolo, bo, out,
                                             TOKENS, DMODEL, DMODEL);
}

// round 6
// speedup vs baseline: 2.5465x; 1.1260x over previous
#include <cuda_runtime.h>
#include <cuda_bf16.h>
#include <math_constants.h>
#include <cstdint>

// Problem constants
#define BATCH   4
#define SEQ     2048
#define DMODEL  1024
#define NHEADS  16
#define HDIM    64
#define TOKENS  (BATCH * SEQ)   // 8192

#define LOG2E 1.4426950408889634f

// ---------------------------------------------------------------------------
// Scratch (allocation-free rule: __device__ globals)
// ---------------------------------------------------------------------------
__device__ __nv_bfloat16 g_xhi[TOKENS * DMODEL];
__device__ __nv_bfloat16 g_xlo[TOKENS * DMODEL];
__device__ __nv_bfloat16 g_qhi[TOKENS * DMODEL];
__device__ __nv_bfloat16 g_qlo[TOKENS * DMODEL];
__device__ __nv_bfloat16 g_khi[TOKENS * DMODEL];
__device__ __nv_bfloat16 g_klo[TOKENS * DMODEL];
__device__ __nv_bfloat16 g_vhi[TOKENS * DMODEL];
__device__ __nv_bfloat16 g_vlo[TOKENS * DMODEL];
__device__ __nv_bfloat16 g_chi[TOKENS * DMODEL];
__device__ __nv_bfloat16 g_clo[TOKENS * DMODEL];
__device__ __nv_bfloat16 g_wqhi[DMODEL * DMODEL];
__device__ __nv_bfloat16 g_wqlo[DMODEL * DMODEL];
__device__ __nv_bfloat16 g_wkhi[DMODEL * DMODEL];
__device__ __nv_bfloat16 g_wklo[DMODEL * DMODEL];
__device__ __nv_bfloat16 g_wvhi[DMODEL * DMODEL];
__device__ __nv_bfloat16 g_wvlo[DMODEL * DMODEL];
__device__ __nv_bfloat16 g_wohi[DMODEL * DMODEL];
__device__ __nv_bfloat16 g_wolo[DMODEL * DMODEL];

// ---------------------------------------------------------------------------
// PTX helpers (sm_80-baseline only: cp.async, ldmatrix, mma.sync)
// ---------------------------------------------------------------------------
__device__ __forceinline__ uint32_t smem_u32(const void* p) {
    uint32_t a;
    asm("{ .reg .u64 t; cvta.to.shared.u64 t, %1; cvt.u32.u64 %0, t; }"
        : "=r"(a) : "l"(p));
    return a;
}

__device__ __forceinline__ void cp_async16(uint32_t smem, const void* gmem) {
    asm volatile("cp.async.cg.shared.global [%0], [%1], 16;\n"
                 :: "r"(smem), "l"(gmem));
}
#define CP_COMMIT() asm volatile("cp.async.commit_group;\n" ::: "memory")
#define CP_WAIT(n)  asm volatile("cp.async.wait_group %0;\n" :: "n"(n) : "memory")

__device__ __forceinline__ void ldsm_x4(uint32_t* r, uint32_t addr) {
    asm volatile("ldmatrix.sync.aligned.m8n8.x4.shared.b16 {%0,%1,%2,%3}, [%4];"
                 : "=r"(r[0]), "=r"(r[1]), "=r"(r[2]), "=r"(r[3]) : "r"(addr));
}

__device__ __forceinline__ void ldsm_x4_trans(uint32_t* r, uint32_t addr) {
    asm volatile("ldmatrix.sync.aligned.m8n8.x4.trans.shared.b16 {%0,%1,%2,%3}, [%4];"
                 : "=r"(r[0]), "=r"(r[1]), "=r"(r[2]), "=r"(r[3]) : "r"(addr));
}

__device__ __forceinline__ void mma_bf16(float* c, const uint32_t* a,
                                         uint32_t b0, uint32_t b1) {
    asm volatile(
        "mma.sync.aligned.m16n8k16.row.col.f32.bf16.bf16.f32 "
        "{%0,%1,%2,%3}, {%4,%5,%6,%7}, {%8,%9}, {%0,%1,%2,%3};"
        : "+f"(c[0]), "+f"(c[1]), "+f"(c[2]), "+f"(c[3])
        : "r"(a[0]), "r"(a[1]), "r"(a[2]), "r"(a[3]), "r"(b0), "r"(b1));
}

__device__ __forceinline__ uint32_t pack_bf16(float x, float y) {
    __nv_bfloat162 t = __floats2bfloat162_rn(x, y);
    return *(uint32_t*)&t;
}

// ---------------------------------------------------------------------------
// Split fp32 -> (bf16 hi, bf16 lo).
// ---------------------------------------------------------------------------
__global__ void split_bf16_kernel(const float* __restrict__ in,
                                  __nv_bfloat16* __restrict__ hi,
                                  __nv_bfloat16* __restrict__ lo, int n)
{
    int i = (blockIdx.x * blockDim.x + threadIdx.x) * 4;
    if (i >= n) return;
    float4 v = *(const float4*)(in + i);
    __nv_bfloat16 h0 = __float2bfloat16(v.x);
    __nv_bfloat16 h1 = __float2bfloat16(v.y);
    __nv_bfloat16 h2 = __float2bfloat16(v.z);
    __nv_bfloat16 h3 = __float2bfloat16(v.w);
    __nv_bfloat16 l0 = __float2bfloat16(v.x - __bfloat162float(h0));
    __nv_bfloat16 l1 = __float2bfloat16(v.y - __bfloat162float(h1));
    __nv_bfloat16 l2 = __float2bfloat16(v.z - __bfloat162float(h2));
    __nv_bfloat16 l3 = __float2bfloat16(v.w - __bfloat162float(h3));
    ((__nv_bfloat162*)(hi + i))[0] = __nv_bfloat162(h0, h1);
    ((__nv_bfloat162*)(hi + i))[1] = __nv_bfloat162(h2, h3);
    ((__nv_bfloat162*)(lo + i))[0] = __nv_bfloat162(l0, l1);
    ((__nv_bfloat162*)(lo + i))[1] = __nv_bfloat162(l2, l3);
}

// ---------------------------------------------------------------------------
// Tensor-core bf16x3 GEMM (NT): C = A B^T (+bias).
// CTA 128x128, BK=32, 8 warps (2x4), warp tile 64x32.
// 2-stage cp.async pipeline (81,920 B SMEM -> 2 CTAs/SM).
// Output: either fp32 C (+bias) or bf16 hi/lo split (Chi/Clo).
// ---------------------------------------------------------------------------
#define GK_BK       32
#define GK_ROW_B    80
#define GK_TILE_B   (128 * GK_ROW_B)
#define GK_STAGE_B  (4 * GK_TILE_B)        // 40960
#define GK_STAGES   2
#define GK_SMEM     (GK_STAGES * GK_STAGE_B)  // 81920

__global__ __launch_bounds__(256) void gemm_mma_bf16x3(
    const __nv_bfloat16* __restrict__ Ahi, const __nv_bfloat16* __restrict__ Alo,
    const __nv_bfloat16* __restrict__ Bhi, const __nv_bfloat16* __restrict__ Blo,
    const float* __restrict__ bias, float* __restrict__ C,
    __nv_bfloat16* __restrict__ Chi, __nv_bfloat16* __restrict__ Clo,
    int M, int N, int K)
{
    extern __shared__ char smem[];
    const uint32_t sbase = smem_u32(smem);
    const int tid  = threadIdx.x;
    const int wid  = tid >> 5;
    const int lane = tid & 31;
    const int warp_m = wid >> 2;
    const int warp_n = wid & 3;
    const int bm = blockIdx.y * 128;
    const int bn = blockIdx.x * 128;

    const __nv_bfloat16* srcs[4] = {Ahi, Alo, Bhi, Blo};
    const int nchunks = K / GK_BK;

    float acc[4][4][4];
#pragma unroll
    for (int i = 0; i < 4; i++)
#pragma unroll
        for (int j = 0; j < 4; j++)
#pragma unroll
            for (int r = 0; r < 4; r++) acc[i][j][r] = 0.f;

    auto load_chunk = [&](int c, int st) {
        const int k0 = c * GK_BK;
#pragma unroll
        for (int t = 0; t < 4; t++) {
            const __nv_bfloat16* src = srcs[t];
            const int rbase = (t < 2) ? bm : bn;
            const uint32_t tb = sbase + st * GK_STAGE_B + t * GK_TILE_B;
#pragma unroll
            for (int i = tid; i < 512; i += 256) {
                const int r = i >> 2;
                const int q = i & 3;
                cp_async16(tb + r * GK_ROW_B + q * 16,
                           src + (size_t)(rbase + r) * K + k0 + q * 8);
            }
        }
        CP_COMMIT();
    };

    load_chunk(0, 0);

    const uint32_t lrow16 = (uint32_t)(lane & 15);
    const uint32_t lcolb  = (uint32_t)((lane >> 4) << 4);

    for (int c = 0; c < nchunks; c++) {
        const int st = c & 1;
        CP_WAIT(0);
        __syncthreads();
        if (c + 1 < nchunks) load_chunk(c + 1, (c + 1) & 1);

        const uint32_t stg = sbase + st * GK_STAGE_B;
        const uint32_t a_r = (uint32_t)(warp_m * 64) + lrow16;
        const uint32_t b_r = (uint32_t)(warp_n * 32) + lrow16;

#pragma unroll
        for (int ks = 0; ks < 2; ks++) {
            const uint32_t kb = lcolb + ks * 32;
            uint32_t ah[4][4], al[4][4], bh[2][4], bl[2][4];
#pragma unroll
            for (int mi = 0; mi < 4; mi++) {
                uint32_t ro = (a_r + mi * 16) * GK_ROW_B + kb;
                ldsm_x4(ah[mi], stg + 0 * GK_TILE_B + ro);
                ldsm_x4(al[mi], stg + 1 * GK_TILE_B + ro);
            }
#pragma unroll
            for (int p = 0; p < 2; p++) {
                uint32_t ro = (b_r + p * 16) * GK_ROW_B + kb;
                ldsm_x4(bh[p], stg + 2 * GK_TILE_B + ro);
                ldsm_x4(bl[p], stg + 3 * GK_TILE_B + ro);
            }
#pragma unroll
            for (int mi = 0; mi < 4; mi++)
#pragma unroll
                for (int ni = 0; ni < 4; ni++) {
                    const int p = ni >> 1, s = ni & 1;
                    mma_bf16(acc[mi][ni], ah[mi], bh[p][s], bh[p][s + 2]);
                    mma_bf16(acc[mi][ni], ah[mi], bl[p][s], bl[p][s + 2]);
                    mma_bf16(acc[mi][ni], al[mi], bh[p][s], bh[p][s + 2]);
                }
        }
        __syncthreads();
    }

    const int er = lane >> 2;
    const int ec = (lane & 3) * 2;
    if (C) {
        // fp32 output + bias
#pragma unroll
        for (int mi = 0; mi < 4; mi++) {
            const int row0 = bm + warp_m * 64 + mi * 16 + er;
#pragma unroll
            for (int ni = 0; ni < 4; ni++) {
                const int col = bn + warp_n * 32 + ni * 8 + ec;
                float b0 = 0.f, b1 = 0.f;
                if (bias) { b0 = bias[col]; b1 = bias[col + 1]; }
                float2 v0 = make_float2(acc[mi][ni][0] + b0, acc[mi][ni][1] + b1);
                float2 v1 = make_float2(acc[mi][ni][2] + b0, acc[mi][ni][3] + b1);
                *(float2*)(C + (size_t)row0 * N + col)       = v0;
                *(float2*)(C + (size_t)(row0 + 8) * N + col) = v1;
            }
        }
    } else {
        // bf16 hi/lo split output
#pragma unroll
        for (int mi = 0; mi < 4; mi++) {
            const int row0 = bm + warp_m * 64 + mi * 16 + er;
#pragma unroll
            for (int ni = 0; ni < 4; ni++) {
                const int col = bn + warp_n * 32 + ni * 8 + ec;
                float a0 = acc[mi][ni][0], a1 = acc[mi][ni][1];
                float a2 = acc[mi][ni][2], a3 = acc[mi][ni][3];
                float h0 = __bfloat162float(__float2bfloat16(a0));
                float h1 = __bfloat162float(__float2bfloat16(a1));
                float h2 = __bfloat162float(__float2bfloat16(a2));
                float h3 = __bfloat162float(__float2bfloat16(a3));
                *(uint32_t*)(Chi + (size_t)row0 * N + col)       = pack_bf16(a0, a1);
                *(uint32_t*)(Clo + (size_t)row0 * N + col)       = pack_bf16(a0 - h0, a1 - h1);
                *(uint32_t*)(Chi + (size_t)(row0 + 8) * N + col) = pack_bf16(a2, a3);
                *(uint32_t*)(Clo + (size_t)(row0 + 8) * N + col) = pack_bf16(a2 - h2, a3 - h3);
            }
        }
    }
}

// ---------------------------------------------------------------------------
// Tensor-core flash attention (causal), bf16x3 MMA, fp32 softmax.
// Inputs: Q/K/V as bf16 hi/lo splits [token, DMODEL]. Output: ctx hi/lo.
// CTA = 128 q rows of one (b,h); 8 warps, warp = 16 q rows x full key range.
// Double-buffered cp.async K/V tiles (64 keys), pitch 72 bf16 (144 B).
// C-frag layout (m16n8): c0=(r,c), c1=(r,c+1), c2=(r+8,c), c3=(r+8,c+1).
// ---------------------------------------------------------------------------
#define FA_PITCH   72
#define FA_ARR_B   (64 * FA_PITCH * 2)      // 9216 bytes per array
#define FA_STAGE_B (4 * FA_ARR_B)           // 36864 (khi, klo, vhi, vlo)
#define FA_SMEM    (2 * FA_STAGE_B)         // 73728

__global__ __launch_bounds__(256) void flash_mma_kernel(
    const __nv_bfloat16* __restrict__ Qhi, const __nv_bfloat16* __restrict__ Qlo,
    const __nv_bfloat16* __restrict__ Khi, const __nv_bfloat16* __restrict__ Klo,
    const __nv_bfloat16* __restrict__ Vhi, const __nv_bfloat16* __restrict__ Vlo,
    __nv_bfloat16* __restrict__ Chi, __nv_bfloat16* __restrict__ Clo)
{
    extern __shared__ char fsm[];
    const uint32_t sbase = smem_u32(fsm);

    const int tid  = threadIdx.x;
    const int wid  = tid >> 5;
    const int lane = tid & 31;
    const int qt = blockIdx.x;     // 0..15
    const int h  = blockIdx.y;
    const int b  = blockIdx.z;

    const int q0_tok = b * SEQ + qt * 128;
    const int qrow_w = qt * 128 + wid * 16;

    // ---- Q A-fragments (hi/lo), loaded once, scaled by 1/8 (exact) ----
    uint32_t qhi[4][4], qlo[4][4];
    {
        const __nv_bfloat16* Qh = Qhi + (size_t)(q0_tok + wid * 16) * DMODEL + h * HDIM;
        const __nv_bfloat16* Ql = Qlo + (size_t)(q0_tok + wid * 16) * DMODEL + h * HDIM;
        const __nv_bfloat162 s2 = __floats2bfloat162_rn(0.125f, 0.125f);
        const int r = lane >> 2;
        const int c = (lane & 3) * 2;
#pragma unroll
        for (int t = 0; t < 4; t++)
#pragma unroll
            for (int i = 0; i < 4; i++) {
                const int rr = r + (i & 1) * 8;
                const int cc = t * 16 + c + (i >> 1) * 8;
                __nv_bfloat162 hv = *(const __nv_bfloat162*)(Qh + (size_t)rr * DMODEL + cc);
                __nv_bfloat162 lv = *(const __nv_bfloat162*)(Ql + (size_t)rr * DMODEL + cc);
                hv = __hmul2(hv, s2);
                lv = __hmul2(lv, s2);
                qhi[t][i] = *(uint32_t*)&hv;
                qlo[t][i] = *(uint32_t*)&lv;
            }
    }

    float o[8][4];
    float m[2], l[2];
#pragma unroll
    for (int i = 0; i < 8; i++)
#pragma unroll
        for (int j = 0; j < 4; j++) o[i][j] = 0.f;
    m[0] = m[1] = -CUDART_INF_F;
    l[0] = l[1] = 0.f;

    // ldmatrix lane offsets (bytes)
    const uint32_t k_loff = (uint32_t)(((lane & 7) + ((lane >> 4) << 3)) * (FA_PITCH * 2)
                                       + (((lane >> 3) & 1) << 4));
    const uint32_t v_loff = (uint32_t)(((lane & 7) + (((lane >> 3) & 1) << 3)) * (FA_PITCH * 2)
                                       + ((lane >> 4) << 4));

    const __nv_bfloat16* kv_srcs[4] = {
        Khi + h * HDIM, Klo + h * HDIM, Vhi + h * HDIM, Vlo + h * HDIM };

    auto load_tile = [&](int kt, int stg) {
        const size_t tok0 = (size_t)(b * SEQ + kt * 64);
        const uint32_t sb = sbase + stg * FA_STAGE_B;
#pragma unroll
        for (int t = 0; t < 4; t++) {
            const __nv_bfloat16* src = kv_srcs[t] + tok0 * DMODEL;
            const uint32_t db = sb + t * FA_ARR_B;
#pragma unroll
            for (int i = tid; i < 512; i += 256) {
                const int r  = i >> 3;
                const int c8 = i & 7;
                cp_async16(db + r * (FA_PITCH * 2) + c8 * 16,
                           src + (size_t)r * DMODEL + c8 * 8);
            }
        }
        CP_COMMIT();
    };

    const int nkt = 2 * qt + 2;

    load_tile(0, 0);

    for (int kt = 0; kt < nkt; kt++) {
        const int kb = kt * 64;
        const int stg = kt & 1;
        CP_WAIT(0);
        __syncthreads();
        if (kt + 1 < nkt) load_tile(kt + 1, stg ^ 1);

        // Fully-masked tile for this warp?
        if (kb > qrow_w + 15) continue;

        const uint32_t ks_hi_b = sbase + stg * FA_STAGE_B;
        const uint32_t ks_lo_b = ks_hi_b + FA_ARR_B;
        const uint32_t vs_hi_b = ks_hi_b + 2 * FA_ARR_B;
        const uint32_t vs_lo_b = ks_hi_b + 3 * FA_ARR_B;

        // ---- S = Q K^T (bf16x3), warp tile 16 x 64 ----
        float s[8][4];
#pragma unroll
        for (int i = 0; i < 8; i++)
#pragma unroll
            for (int j = 0; j < 4; j++) s[i][j] = 0.f;

#pragma unroll
        for (int t = 0; t < 4; t++) {
#pragma unroll
            for (int pp = 0; pp < 4; pp++) {
                const uint32_t ro = (uint32_t)(pp * 16 * (FA_PITCH * 2) + t * 32) + k_loff;
                uint32_t kh[4], kl[4];
                ldsm_x4(kh, ks_hi_b + ro);
                ldsm_x4(kl, ks_lo_b + ro);
                mma_bf16(s[2 * pp],     qhi[t], kh[0], kh[1]);
                mma_bf16(s[2 * pp],     qhi[t], kl[0], kl[1]);
                mma_bf16(s[2 * pp],     qlo[t], kh[0], kh[1]);
                mma_bf16(s[2 * pp + 1], qhi[t], kh[2], kh[3]);
                mma_bf16(s[2 * pp + 1], qhi[t], kl[2], kl[3]);
                mma_bf16(s[2 * pp + 1], qlo[t], kh[2], kh[3]);
            }
        }

        // ---- causal mask: c-reg i -> row = g + (i>>1)*8, col = c + (i&1) ----
        const int row_g0 = qrow_w + (lane >> 2);
        if (kb + 63 > qrow_w) {
#pragma unroll
            for (int nt = 0; nt < 8; nt++) {
                const int colb = kb + nt * 8 + (lane & 3) * 2;
#pragma unroll
                for (int i = 0; i < 4; i++) {
                    const int row = row_g0 + (i >> 1) * 8;
                    const int col = colb + (i & 1);
                    if (col > row) s[nt][i] = -CUDART_INF_F;
                }
            }
        }

        // ---- online softmax: regs {0,1} -> row r (idx 0), {2,3} -> r+8 (idx 1) ----
        float rmax[2];
        rmax[0] = rmax[1] = -CUDART_INF_F;
#pragma unroll
        for (int nt = 0; nt < 8; nt++) {
            rmax[0] = fmaxf(rmax[0], fmaxf(s[nt][0], s[nt][1]));
            rmax[1] = fmaxf(rmax[1], fmaxf(s[nt][2], s[nt][3]));
        }
#pragma unroll
        for (int off = 1; off <= 2; off <<= 1) {
            rmax[0] = fmaxf(rmax[0], __shfl_xor_sync(0xffffffffu, rmax[0], off));
            rmax[1] = fmaxf(rmax[1], __shfl_xor_sync(0xffffffffu, rmax[1], off));
        }

        float alpha[2], rsum[2];
#pragma unroll
        for (int i = 0; i < 2; i++) {
            float mn = fmaxf(m[i], rmax[i]);
            alpha[i] = exp2f((m[i] - mn) * LOG2E);
            m[i] = mn;
            rsum[i] = 0.f;
        }

#pragma unroll
        for (int nt = 0; nt < 8; nt++) {
            s[nt][0] = exp2f((s[nt][0] - m[0]) * LOG2E);
            s[nt][1] = exp2f((s[nt][1] - m[0]) * LOG2E);
            s[nt][2] = exp2f((s[nt][2] - m[1]) * LOG2E);
            s[nt][3] = exp2f((s[nt][3] - m[1]) * LOG2E);
            rsum[0] += s[nt][0] + s[nt][1];
            rsum[1] += s[nt][2] + s[nt][3];
        }
#pragma unroll
        for (int off = 1; off <= 2; off <<= 1) {
            rsum[0] += __shfl_xor_sync(0xffffffffu, rsum[0], off);
            rsum[1] += __shfl_xor_sync(0xffffffffu, rsum[1], off);
        }
        l[0] = l[0] * alpha[0] + rsum[0];
        l[1] = l[1] * alpha[1] + rsum[1];
#pragma unroll
        for (int nt = 0; nt < 8; nt++) {
            o[nt][0] *= alpha[0]; o[nt][1] *= alpha[0];
            o[nt][2] *= alpha[1]; o[nt][3] *= alpha[1];
        }

        // ---- O += P V (bf16x3); P C-frags -> A-frags in registers ----
#pragma unroll
        for (int t = 0; t < 4; t++) {
            uint32_t ahi[4], alo[4];
            {
                float x0 = s[2 * t][0],     x1 = s[2 * t][1];
                float x2 = s[2 * t][2],     x3 = s[2 * t][3];
                float y0 = s[2 * t + 1][0], y1 = s[2 * t + 1][1];
                float y2 = s[2 * t + 1][2], y3 = s[2 * t + 1][3];
                float hx0 = __bfloat162float(__float2bfloat16(x0));
                float hx1 = __bfloat162float(__float2bfloat16(x1));
                float hx2 = __bfloat162float(__float2bfloat16(x2));
                float hx3 = __bfloat162float(__float2bfloat16(x3));
                float hy0 = __bfloat162float(__float2bfloat16(y0));
                float hy1 = __bfloat162float(__float2bfloat16(y1));
                float hy2 = __bfloat162float(__float2bfloat16(y2));
                float hy3 = __bfloat162float(__float2bfloat16(y3));
                ahi[0] = pack_bf16(x0, x1);  alo[0] = pack_bf16(x0 - hx0, x1 - hx1);
                ahi[1] = pack_bf16(x2, x3);  alo[1] = pack_bf16(x2 - hx2, x3 - hx3);
                ahi[2] = pack_bf16(y0, y1);  alo[2] = pack_bf16(y0 - hy0, y1 - hy1);
                ahi[3] = pack_bf16(y2, y3);  alo[3] = pack_bf16(y2 - hy2, y3 - hy3);
            }
#pragma unroll
            for (int dp = 0; dp < 4; dp++) {
                const uint32_t ro = (uint32_t)(t * 16 * (FA_PITCH * 2) + dp * 32) + v_loff;
                uint32_t bh[4], bl[4];
                ldsm_x4_trans(bh, vs_hi_b + ro);
                ldsm_x4_trans(bl, vs_lo_b + ro);
                mma_bf16(o[2 * dp],     ahi, bh[0], bh[1]);
                mma_bf16(o[2 * dp],     ahi, bl[0], bl[1]);
                mma_bf16(o[2 * dp],     alo, bh[0], bh[1]);
                mma_bf16(o[2 * dp + 1], ahi, bh[2], bh[3]);
                mma_bf16(o[2 * dp + 1], ahi, bl[2], bl[3]);
                mma_bf16(o[2 * dp + 1], alo, bh[2], bh[3]);
            }
        }
    }

    // ---- epilogue: normalize, split to hi/lo, store ctx ----
    const float inv0 = 1.f / l[0];
    const float inv1 = 1.f / l[1];
    const int orow = q0_tok + wid * 16 + (lane >> 2);
    const int colb = h * HDIM + (lane & 3) * 2;
#pragma unroll
    for (int nt = 0; nt < 8; nt++) {
        const int col = colb + nt * 8;
        float v00 = o[nt][0] * inv0, v01 = o[nt][1] * inv0;
        float v10 = o[nt][2] * inv1, v11 = o[nt][3] * inv1;
        float h00 = __bfloat162float(__float2bfloat16(v00));
        float h01 = __bfloat162float(__float2bfloat16(v01));
        float h10 = __bfloat162float(__float2bfloat16(v10));
        float h11 = __bfloat162float(__float2bfloat16(v11));
        *(uint32_t*)(Chi + (size_t)orow * DMODEL + col)       = pack_bf16(v00, v01);
        *(uint32_t*)(Clo + (size_t)orow * DMODEL + col)       = pack_bf16(v00 - h00, v01 - h01);
        *(uint32_t*)(Chi + (size_t)(orow + 8) * DMODEL + col) = pack_bf16(v10, v11);
        *(uint32_t*)(Clo + (size_t)(orow + 8) * DMODEL + col) = pack_bf16(v10 - h10, v11 - h11);
    }
}

// ---------------------------------------------------------------------------
// Launch
// ---------------------------------------------------------------------------
extern "C" void kernel_launch(void* const* d_in, const int* in_sizes, int n_in,
                              void* d_out, int out_size)
{
    const float* x  = (const float*)d_in[0];
    const float* wq = (const float*)d_in[1];
    const float* wk = (const float*)d_in[2];
    const float* wv = (const float*)d_in[3];
    const float* wo = (const float*)d_in[4];
    const float* bo = (const float*)d_in[5];
    float* out = (float*)d_out;

    __nv_bfloat16 *xhi, *xlo, *qhi, *qlo, *khi, *klo, *vhi, *vlo, *chi, *clo;
    __nv_bfloat16 *wqhi, *wqlo, *wkhi, *wklo, *wvhi, *wvlo, *wohi, *wolo;
    cudaGetSymbolAddress((void**)&xhi,  g_xhi);
    cudaGetSymbolAddress((void**)&xlo,  g_xlo);
    cudaGetSymbolAddress((void**)&qhi,  g_qhi);
    cudaGetSymbolAddress((void**)&qlo,  g_qlo);
    cudaGetSymbolAddress((void**)&khi,  g_khi);
    cudaGetSymbolAddress((void**)&klo,  g_klo);
    cudaGetSymbolAddress((void**)&vhi,  g_vhi);
    cudaGetSymbolAddress((void**)&vlo,  g_vlo);
    cudaGetSymbolAddress((void**)&chi,  g_chi);
    cudaGetSymbolAddress((void**)&clo,  g_clo);
    cudaGetSymbolAddress((void**)&wqhi, g_wqhi);
    cudaGetSymbolAddress((void**)&wqlo, g_wqlo);
    cudaGetSymbolAddress((void**)&wkhi, g_wkhi);
    cudaGetSymbolAddress((void**)&wklo, g_wklo);
    cudaGetSymbolAddress((void**)&wvhi, g_wvhi);
    cudaGetSymbolAddress((void**)&wvlo, g_wvlo);
    cudaGetSymbolAddress((void**)&wohi, g_wohi);
    cudaGetSymbolAddress((void**)&wolo, g_wolo);

    const int nx = TOKENS * DMODEL;
    const int nw = DMODEL * DMODEL;

    split_bf16_kernel<<<nx / 4 / 256, 256>>>(x,  xhi,  xlo,  nx);
    split_bf16_kernel<<<nw / 4 / 256, 256>>>(wq, wqhi, wqlo, nw);
    split_bf16_kernel<<<nw / 4 / 256, 256>>>(wk, wkhi, wklo, nw);
    split_bf16_kernel<<<nw / 4 / 256, 256>>>(wv, wvhi, wvlo, nw);
    split_bf16_kernel<<<nw / 4 / 256, 256>>>(wo, wohi, wolo, nw);

    cudaFuncSetAttribute(gemm_mma_bf16x3,
                         cudaFuncAttributeMaxDynamicSharedMemorySize, GK_SMEM);
    dim3 ggrid(DMODEL / 128, TOKENS / 128);
    gemm_mma_bf16x3<<<ggrid, 256, GK_SMEM>>>(xhi, xlo, wqhi, wqlo, nullptr,
                                             nullptr, qhi, qlo,
                                             TOKENS, DMODEL, DMODEL);
    gemm_mma_bf16x3<<<ggrid, 256, GK_SMEM>>>(xhi, xlo, wkhi, wklo, nullptr,
                                             nullptr, khi, klo,
                                             TOKENS, DMODEL, DMODEL);
    gemm_mma_bf16x3<<<ggrid, 256, GK_SMEM>>>(xhi, xlo, wvhi, wvlo, nullptr,
                                             nullptr, vhi, vlo,
                                             TOKENS, DMODEL, DMODEL);

    cudaFuncSetAttribute(flash_mma_kernel,
                         cudaFuncAttributeMaxDynamicSharedMemorySize, FA_SMEM);
    flash_mma_kernel<<<dim3(SEQ / 128, NHEADS, BATCH), 256, FA_SMEM>>>(
        qhi, qlo, khi, klo, vhi, vlo, chi, clo);

    gemm_mma_bf16x3<<<ggrid, 256, GK_SMEM>>>(chi, clo, wohi, wolo, bo,
                                             out, nullptr, nullptr,
                                             TOKENS, DMODEL, DMODEL);
}